// round 17
// baseline (speedup 1.0000x reference)
#include <cuda_runtime.h>
#include <cuda_fp16.h>
#include <math.h>
#include <stdint.h>

// ---------------- problem constants ----------------
#define BATCH     32
#define HDIM      64
#define WDIM      64
#define CDIM      256
#define NHEADS    8
#define WS        8
#define SS        4
#define BWIN      (BATCH*64)          // 2048
#define ROWS      (BATCH*HDIM*WDIM)   // 131072
#define HIDDEN    1024
#define CPBH      512

// fp16 GEMM tiling (unfused): CTA 128x128, BK=32 (64B rows), 256 thr, warp 64x32,
// 4-stage cp.async ring (R15 measured-best pattern).
#define ROWB     80                    // bytes per smem row (64 data + 16 pad)
#define SEC_B    10240                 // B section offset (128*80)
#define STAGE_B  20480
#define SMEM_GEMM (4*STAGE_B)          // 81920 -> 2 CTAs/SM

// fused LN GEMM: CTA 128x256, 512 thr (16 warps 2Mx8N), 4-stage ring
#define SEC2_B   10240                 // B section offset within fused stage
#define STG2_B   30720                 // A 128*80 + B 256*80
#define SMEM_LN  (4*STG2_B)            // 122880 -> 1 CTA/SM

// ---------------- scratch (device globals, no alloc) ----------------
__device__ float  g_qkv[3u*2048u*8u*64u*32u];          // fp32 (attention precision)
__device__ __align__(128) __half g_attn_h[(size_t)131072*256];
__device__ float  g_x1[(size_t)131072*256];
__device__ __align__(128) __half g_x1h[(size_t)131072*256];
__device__ __align__(128) __half g_hidh[(size_t)131072*1024];
__device__ __align__(128) __half g_xh[(size_t)131072*256];
__device__ float  g_bias_table[225*8];
__device__ float  g_rpb[8*64*64];
__device__ int    g_gather[131072];
__device__ __align__(128) __half g_wq[768*256];
__device__ __align__(128) __half g_wp[256*256];
__device__ __align__(128) __half g_w1[1024*256];
__device__ __align__(128) __half g_w2[256*1024];

// ---------------- helpers ----------------
__device__ __forceinline__ uint32_t smem_u32(const void* p){
    uint32_t a;
    asm("{ .reg .u64 t; cvta.to.shared.u64 t, %1; cvt.u32.u64 %0, t; }" : "=r"(a) : "l"(p));
    return a;
}
#define CP16(dst, src) asm volatile("cp.async.cg.shared.global [%0], [%1], 16;" :: "r"(dst), "l"(src))
#define CP_COMMIT()    asm volatile("cp.async.commit_group;" ::: "memory")
#define CP_WAIT2()     asm volatile("cp.async.wait_group 2;" ::: "memory")
#define CP_WAIT0()     asm volatile("cp.async.wait_group 0;" ::: "memory")

__device__ __forceinline__ void mma_f16(float* c, const uint32_t* a, const uint32_t* b){
    asm volatile("mma.sync.aligned.m16n8k16.row.col.f32.f16.f16.f32 "
      "{%0,%1,%2,%3}, {%4,%5,%6,%7}, {%8,%9}, {%0,%1,%2,%3};\n"
      : "+f"(c[0]), "+f"(c[1]), "+f"(c[2]), "+f"(c[3])
      : "r"(a[0]), "r"(a[1]), "r"(a[2]), "r"(a[3]), "r"(b[0]), "r"(b[1]));
}
__device__ __forceinline__ float gelu_t(float x){
    float x3 = x*x*x;
    float t  = tanhf(0.7978845608028654f * (x + 0.044715f*x3));
    return 0.5f * x * (1.0f + t);
}
__device__ __forceinline__ float warp_sum(float v){
#pragma unroll
    for (int o = 16; o > 0; o >>= 1) v += __shfl_xor_sync(0xffffffffu, v, o);
    return v;
}

// ---------------- fused setup: gather index + x -> fp16 ----------------
__global__ void k_setup(const float* __restrict__ x){
    int gid = blockIdx.x * 256 + threadIdx.x;
    size_t i = (size_t)gid * 4;
    float4 v = *(const float4*)(x + i);
    __half2* oh = (__half2*)(g_xh + i);
    oh[0] = __floats2half2_rn(v.x, v.y);
    oh[1] = __floats2half2_rn(v.z, v.w);
    if (gid < ROWS){
        int b_  = gid >> 6;
        int n   = gid & 63;
        int b   = b_ >> 6;
        int wid = b_ & 63;
        int h = ((wid >> 3)*8 + (n >> 3) + SS) & 63;
        int w = ((wid & 7)*8 + (n & 7) + SS) & 63;
        g_gather[gid] = b*(HDIM*WDIM) + h*WDIM + w;
    }
}

// ---------------- fused CPB MLP + rpb table (single block) ----------------
__device__ __forceinline__ float cpb_coord(int c){
    float t = (float)c * (8.0f/7.0f);
    float v = log2f(fabsf(t) + 1.0f) * (1.0f/3.0f);
    return t < 0.f ? -v : v;
}
__global__ void k_cpb_rpb(const float* __restrict__ w1, const float* __restrict__ b1,
                          const float* __restrict__ w2){
    int p = threadIdx.x;
    if (p < 225){
        float t0 = cpb_coord(p/15 - 7);
        float t1 = cpb_coord(p%15 - 7);
        float out[8];
#pragma unroll
        for (int h = 0; h < 8; h++) out[h] = 0.f;
        for (int j = 0; j < CPBH; j++){
            float hdn = fmaxf(t0*w1[j] + t1*w1[CPBH + j] + b1[j], 0.f);
#pragma unroll
            for (int h = 0; h < 8; h++) out[h] = fmaf(hdn, w2[j*8 + h], out[h]);
        }
#pragma unroll
        for (int h = 0; h < 8; h++) g_bias_table[p*8 + h] = out[h];
    }
    __syncthreads();
    for (int idx = threadIdx.x; idx < 8*64*64; idx += 256){
        int h = idx >> 12;
        int n = (idx >> 6) & 63;
        int m = idx & 63;
        int dh = (n>>3) - (m>>3) + 7;
        int dw = (n&7)  - (m&7)  + 7;
        float b = g_bias_table[(dh*15 + dw)*8 + h];
        g_rpb[idx] = 16.0f / (1.0f + expf(-b));
    }
}

// ---------------- fused weight transposes: W[K,N] -> half Wt[N,K] ----------------
__global__ void k_transpose_all(const float* __restrict__ w_qkv,
                                const float* __restrict__ w_proj,
                                const float* __restrict__ w_fc1,
                                const float* __restrict__ w_fc2){
    const float* W; __half* Wt; int K, N;
    switch (blockIdx.z){
        case 0: W = w_qkv;  Wt = g_wq; K = 256;  N = 768;  break;
        case 1: W = w_proj; Wt = g_wp; K = 256;  N = 256;  break;
        case 2: W = w_fc1;  Wt = g_w1; K = 256;  N = 1024; break;
        default:W = w_fc2;  Wt = g_w2; K = 1024; N = 256;  break;
    }
    int n0 = blockIdx.x*32, k0 = blockIdx.y*32;
    if (n0 >= N || k0 >= K) return;
    __shared__ float t[32][33];
    for (int r = threadIdx.y; r < 32; r += 8)
        t[r][threadIdx.x] = W[(size_t)(k0+r)*N + n0 + threadIdx.x];
    __syncthreads();
    for (int r = threadIdx.y; r < 32; r += 8)
        Wt[(size_t)(n0+r)*K + k0 + threadIdx.x] = __float2half_rn(t[threadIdx.x][r]);
}

// ============================================================================
// fp16 GEMM core pieces
// ============================================================================

__device__ __forceinline__ void compute_tile_h(const char* sA, const char* sB,
        int wm, int wn, int lr, int lc, float acc[4][4][4]){
#pragma unroll
    for (int ks = 0; ks < 2; ks++){
        const int kb = ks*32 + lc*4;
        uint32_t a[4][4], b[4][2];
#pragma unroll
        for (int mt = 0; mt < 4; mt++){
            int r = wm + mt*16 + lr;
            a[mt][0] = *(const uint32_t*)(sA + r*ROWB + kb);
            a[mt][1] = *(const uint32_t*)(sA + (r+8)*ROWB + kb);
            a[mt][2] = *(const uint32_t*)(sA + r*ROWB + kb + 16);
            a[mt][3] = *(const uint32_t*)(sA + (r+8)*ROWB + kb + 16);
        }
#pragma unroll
        for (int nt = 0; nt < 4; nt++){
            int c = wn + nt*8 + lr;
            b[nt][0] = *(const uint32_t*)(sB + c*ROWB + kb);
            b[nt][1] = *(const uint32_t*)(sB + c*ROWB + kb + 16);
        }
#pragma unroll
        for (int mt = 0; mt < 4; mt++)
#pragma unroll
            for (int nt = 0; nt < 4; nt++)
                mma_f16(acc[mt][nt], a[mt], b[nt]);
    }
}

__device__ __forceinline__ void issue_stage_h(uint32_t da, uint32_t db,
        const char* ap, const char* bp, int i){
    CP16(da,      ap + i*64);
    CP16(da + 16, ap + i*64 + 16);
    CP16(db,      bp + i*64);
    CP16(db + 16, bp + i*64 + 16);
}

// ---------------- unfused GEMM (QKV / FC1): R15 pattern ----------------
template<int ACT, int HOUT>
__global__ __launch_bounds__(256, 2) void gemm_h(const __half* __restrict__ A,
        const __half* __restrict__ Bt, const float* __restrict__ bias,
        void* __restrict__ Cv, int K, int Nn){
    extern __shared__ char smc[];
    uint32_t sbase = smem_u32(smc);
    const int tid = threadIdx.x;
    const int wid = tid >> 5, lane = tid & 31;
    const int wm = (wid >> 2)*64, wn = (wid & 3)*32;
    const int lr = lane >> 2, lc = lane & 3;
    const int bm = blockIdx.y * 128;
    const int bn = blockIdx.x * 128;

    const int srow = tid >> 1, soff = (tid & 1)*32;
    const char* ap = (const char*)(A  + (size_t)(bm + srow)*K) + soff;
    const char* bp = (const char*)(Bt + (size_t)(bn + srow)*K) + soff;
    const uint32_t da = sbase + srow*ROWB + soff;
    const uint32_t db = sbase + SEC_B + srow*ROWB + soff;

    float acc[4][4][4];
#pragma unroll
    for (int mt = 0; mt < 4; mt++)
#pragma unroll
        for (int nt = 0; nt < 4; nt++)
#pragma unroll
            for (int q = 0; q < 4; q++) acc[mt][nt][q] = 0.f;

    const int S = K / 32;
#pragma unroll
    for (int p = 0; p < 3; p++){
        issue_stage_h(da + p*STAGE_B, db + p*STAGE_B, ap, bp, p);
        CP_COMMIT();
    }

    for (int i = 0; i < S; i++){
        CP_WAIT2();
        __syncthreads();
        const char* st = smc + (i & 3)*STAGE_B;
        compute_tile_h(st, st + SEC_B, wm, wn, lr, lc, acc);
        __syncthreads();
        if (i + 3 < S){
            int s = (i + 3) & 3;
            issue_stage_h(da + s*STAGE_B, db + s*STAGE_B, ap, bp, i + 3);
        }
        CP_COMMIT();
    }

#pragma unroll
    for (int mt = 0; mt < 4; mt++){
        int r0 = bm + wm + mt*16 + lr;
#pragma unroll
        for (int nt = 0; nt < 4; nt++){
            int c0 = bn + wn + nt*8 + lc*2;
            float b0 = bias[c0], b1 = bias[c0+1];
            float v0 = acc[mt][nt][0] + b0, v1 = acc[mt][nt][1] + b1;
            float v2 = acc[mt][nt][2] + b0, v3 = acc[mt][nt][3] + b1;
            if (ACT == 1){ v0=gelu_t(v0); v1=gelu_t(v1); v2=gelu_t(v2); v3=gelu_t(v3); }
            if (HOUT){
                __half* C = (__half*)Cv;
                *(__half2*)(C + (size_t)r0*Nn + c0)     = __floats2half2_rn(v0, v1);
                *(__half2*)(C + (size_t)(r0+8)*Nn + c0) = __floats2half2_rn(v2, v3);
            } else {
                float* C = (float*)Cv;
                *(float2*)(C + (size_t)r0*Nn + c0)     = make_float2(v0, v1);
                *(float2*)(C + (size_t)(r0+8)*Nn + c0) = make_float2(v2, v3);
            }
        }
    }
}

// QKV: A rows gathered from g_xh, fp32 scatter epilogue into g_qkv
__global__ __launch_bounds__(256, 2) void gemm_h_qkv(const __half* __restrict__ Xh,
        const __half* __restrict__ Bt, const float* __restrict__ qb,
        const float* __restrict__ vb){
    extern __shared__ char smc[];
    uint32_t sbase = smem_u32(smc);
    const int tid = threadIdx.x;
    const int wid = tid >> 5, lane = tid & 31;
    const int wm = (wid >> 2)*64, wn = (wid & 3)*32;
    const int lr = lane >> 2, lc = lane & 3;
    const int bm = blockIdx.y * 128;
    const int bn = blockIdx.x * 128;
    const int K = 256;

    const int srow = tid >> 1, soff = (tid & 1)*32;
    const char* ap = (const char*)(Xh + (size_t)g_gather[bm + srow]*K) + soff;
    const char* bp = (const char*)(Bt + (size_t)(bn + srow)*K) + soff;
    const uint32_t da = sbase + srow*ROWB + soff;
    const uint32_t db = sbase + SEC_B + srow*ROWB + soff;

    float acc[4][4][4];
#pragma unroll
    for (int mt = 0; mt < 4; mt++)
#pragma unroll
        for (int nt = 0; nt < 4; nt++)
#pragma unroll
            for (int q = 0; q < 4; q++) acc[mt][nt][q] = 0.f;

    const int S = K / 32;   // 8
#pragma unroll
    for (int p = 0; p < 3; p++){
        issue_stage_h(da + p*STAGE_B, db + p*STAGE_B, ap, bp, p);
        CP_COMMIT();
    }

    for (int i = 0; i < S; i++){
        CP_WAIT2();
        __syncthreads();
        const char* st = smc + (i & 3)*STAGE_B;
        compute_tile_h(st, st + SEC_B, wm, wn, lr, lc, acc);
        __syncthreads();
        if (i + 3 < S){
            int s = (i + 3) & 3;
            issue_stage_h(da + s*STAGE_B, db + s*STAGE_B, ap, bp, i + 3);
        }
        CP_COMMIT();
    }

#pragma unroll
    for (int mt = 0; mt < 4; mt++){
        int r0 = bm + wm + mt*16 + lr;
        int b0_ = r0 >> 6, n0 = r0 & 63;
        int b1_ = (r0+8) >> 6, n1 = (r0+8) & 63;
#pragma unroll
        for (int nt = 0; nt < 4; nt++){
            int c0 = bn + wn + nt*8 + lc*2;
            int s2 = c0 >> 8, rem = c0 & 255;
            int h = rem >> 5, d = rem & 31;
            float bv0, bv1;
            if (s2 == 0){ bv0 = qb[rem]; bv1 = qb[rem+1]; }
            else if (s2 == 2){ bv0 = vb[rem]; bv1 = vb[rem+1]; }
            else { bv0 = 0.f; bv1 = 0.f; }
            size_t hb = ((size_t)(s2*BWIN)*NHEADS + (size_t)h)*2048 + d;
            *(float2*)(g_qkv + hb + ((size_t)b0_*NHEADS)*2048 + n0*32) =
                make_float2(acc[mt][nt][0] + bv0, acc[mt][nt][1] + bv1);
            *(float2*)(g_qkv + hb + ((size_t)b1_*NHEADS)*2048 + n1*32) =
                make_float2(acc[mt][nt][2] + bv0, acc[mt][nt][3] + bv1);
        }
    }
}

// ============================================================================
// fused GEMM + LayerNorm + residual: CTA 128x256, 512 thr (2Mx8N warps).
// GATHER=1: proj+LN1 (A=g_attn_h gathered-order; scatter to natural rows via
//           g_gather; write g_x1 fp32 + g_x1h fp16).
// GATHER=0: FC2+LN2 (natural order; write `out` fp32 only).
// ============================================================================
template<int GATHER>
__global__ __launch_bounds__(512, 1) void gemm_ln(const __half* __restrict__ A,
        const __half* __restrict__ Bt, const float* __restrict__ bias,
        const float* __restrict__ resid, const float* __restrict__ lnsc,
        const float* __restrict__ lnbi, float* __restrict__ outf,
        __half* __restrict__ outh, int K){
    extern __shared__ char smc[];
    uint32_t sbase = smem_u32(smc);
    const int tid = threadIdx.x;
    const int wid = tid >> 5, lane = tid & 31;
    const int wm = (wid >> 3)*64, wn = (wid & 7)*32;
    const int lr = lane >> 2, lc = lane & 3;
    const int bm = blockIdx.x * 128;

    // staging: threads 0..255 -> A (row tid>>1, half tid&1: 2x16B)
    //          threads 256..511 -> B (row tid-256: 4x16B)
    const char* sp; uint32_t sd;
    if (tid < 256){
        int ar = tid >> 1, so = (tid & 1)*32;
        sp = (const char*)(A + (size_t)(bm + ar)*K) + so;
        sd = sbase + ar*ROWB + so;
    } else {
        int br = tid - 256;
        sp = (const char*)(Bt + (size_t)br*K);
        sd = sbase + SEC2_B + br*ROWB;
    }

    float acc[4][4][4];
#pragma unroll
    for (int mt = 0; mt < 4; mt++)
#pragma unroll
        for (int nt = 0; nt < 4; nt++)
#pragma unroll
            for (int q = 0; q < 4; q++) acc[mt][nt][q] = 0.f;

    const int S = K / 32;
#pragma unroll
    for (int p = 0; p < 3; p++){
        uint32_t d = sd + p*STG2_B;
        if (tid < 256){ CP16(d, sp + p*64); CP16(d + 16, sp + p*64 + 16); }
        else {
#pragma unroll
            for (int c = 0; c < 4; c++) CP16(d + c*16, sp + p*64 + c*16);
        }
        CP_COMMIT();
    }

    for (int i = 0; i < S; i++){
        CP_WAIT2();
        __syncthreads();
        const char* st = smc + (i & 3)*STG2_B;
        compute_tile_h(st, st + SEC2_B, wm, wn, lr, lc, acc);
        __syncthreads();
        if (i + 3 < S){
            uint32_t d = sd + ((i + 3) & 3)*STG2_B;
            if (tid < 256){ CP16(d, sp + (i+3)*64); CP16(d + 16, sp + (i+3)*64 + 16); }
            else {
#pragma unroll
                for (int c = 0; c < 4; c++) CP16(d + c*16, sp + (i+3)*64 + c*16);
            }
        }
        CP_COMMIT();
    }
    CP_WAIT0();
    __syncthreads();

    // ---- LN epilogue: partial sums -> smem reduce -> apply ----
    float* redS = (float*)smc;              // [128][33]
    float* redQ = redS + 128*33;            // [128][33]
    float* mus  = redQ + 128*33;            // [128]
    float* isg  = mus + 128;                // [128]
    const int nw = wid & 7;

#pragma unroll
    for (int mt = 0; mt < 4; mt++){
#pragma unroll
        for (int h2 = 0; h2 < 2; h2++){
            int row = wm + mt*16 + lr + h2*8;
            float s = 0.f, q = 0.f;
#pragma unroll
            for (int nt = 0; nt < 4; nt++){
                int c0 = wn + nt*8 + lc*2;
                float v0 = acc[mt][nt][h2*2+0] + bias[c0];
                float v1 = acc[mt][nt][h2*2+1] + bias[c0+1];
                s += v0 + v1;
                q += v0*v0 + v1*v1;
            }
            redS[row*33 + nw*4 + lc] = s;
            redQ[row*33 + nw*4 + lc] = q;
        }
    }
    __syncthreads();
    if (tid < 128){
        float s = 0.f, q = 0.f;
#pragma unroll
        for (int j = 0; j < 32; j++){ s += redS[tid*33 + j]; q += redQ[tid*33 + j]; }
        float mu = s * (1.f/256.f);
        float var = q * (1.f/256.f) - mu*mu;
        mus[tid] = mu;
        isg[tid] = rsqrtf(fmaxf(var, 0.f) + 1e-6f);
    }
    __syncthreads();

#pragma unroll
    for (int mt = 0; mt < 4; mt++){
#pragma unroll
        for (int h2 = 0; h2 < 2; h2++){
            int row = wm + mt*16 + lr + h2*8;
            int grow = bm + row;
            float mu = mus[row], iv = isg[row];
            int drow = GATHER ? g_gather[grow] : grow;
            const float* xr = resid + (size_t)drow*CDIM;
            float* of = outf + (size_t)drow*CDIM;
#pragma unroll
            for (int nt = 0; nt < 4; nt++){
                int c0 = wn + nt*8 + lc*2;
                float v0 = acc[mt][nt][h2*2+0] + bias[c0];
                float v1 = acc[mt][nt][h2*2+1] + bias[c0+1];
                float r0 = xr[c0]   + (v0 - mu)*iv*lnsc[c0]   + lnbi[c0];
                float r1 = xr[c0+1] + (v1 - mu)*iv*lnsc[c0+1] + lnbi[c0+1];
                *(float2*)(of + c0) = make_float2(r0, r1);
                if (GATHER)
                    *(__half2*)(outh + (size_t)drow*CDIM + c0) = __floats2half2_rn(r0, r1);
            }
        }
    }
}

// ---------------- attention: one (window, head) per block, chunked online softmax ----------------
__global__ __launch_bounds__(64) void k_attn(const float* __restrict__ ls){
    const int b_ = blockIdx.x;
    const int hh = blockIdx.y;
    const int n  = threadIdx.x;
    __shared__ float kn[64][32];
    __shared__ float vs[64][32];
    __shared__ int   rg[64];

    const size_t sstride = (size_t)BWIN * NHEADS * 64 * 32;
    const size_t base = ((size_t)b_*NHEADS + hh)*(64*32) + n*32;
    const float* qp = g_qkv + base;
    const float* kp = g_qkv + sstride + base;
    const float* vp = g_qkv + 2*sstride + base;

    float qr[32]; float sacc = 0.f;
#pragma unroll
    for (int d = 0; d < 32; d++){ qr[d] = qp[d]; sacc = fmaf(qr[d], qr[d], sacc); }
    float qi = rsqrtf(fmaxf(sacc, 1e-12f));
#pragma unroll
    for (int d = 0; d < 32; d++) qr[d] *= qi;

    sacc = 0.f; float kr[32];
#pragma unroll
    for (int d = 0; d < 32; d++){ kr[d] = kp[d]; sacc = fmaf(kr[d], kr[d], sacc); }
    float ki = rsqrtf(fmaxf(sacc, 1e-12f));
#pragma unroll
    for (int d = 0; d < 32; d++) kn[n][d] = kr[d]*ki;
#pragma unroll
    for (int d = 0; d < 32; d++) vs[n][d] = vp[d];

    int wid = b_ & 63;
    int gh = (wid >> 3)*8 + (n >> 3);
    int gw = (wid & 7)*8 + (n & 7);
    int hr = gh < 56 ? 0 : (gh < 60 ? 1 : 2);
    int wr = gw < 56 ? 0 : (gw < 60 ? 1 : 2);
    rg[n] = hr*3 + wr;
    __syncthreads();

    float scale = expf(fminf(ls[hh], 4.6051701859880914f));
    const float* rp = g_rpb + (hh*64 + n)*64;
    int myreg = hr*3 + wr;

    float mx = -1e30f, sum = 0.f;
    float acc[32];
#pragma unroll
    for (int d = 0; d < 32; d++) acc[d] = 0.f;

    for (int cb = 0; cb < 64; cb += 16){
        float lg[16]; float cmax = -1e30f;
#pragma unroll
        for (int j = 0; j < 16; j++){
            int m = cb + j;
            float dot = 0.f;
#pragma unroll
            for (int d = 0; d < 32; d++) dot = fmaf(qr[d], kn[m][d], dot);
            float v = fmaf(dot, scale, rp[m]);
            if (rg[m] != myreg) v -= 100.f;
            lg[j] = v;
            cmax = fmaxf(cmax, v);
        }
        float nm = fmaxf(mx, cmax);
        float corr = expf(mx - nm);
        sum *= corr;
#pragma unroll
        for (int d = 0; d < 32; d++) acc[d] *= corr;
#pragma unroll
        for (int j = 0; j < 16; j++){
            float p = expf(lg[j] - nm);
            sum += p;
            const float* vr = vs[cb + j];
#pragma unroll
            for (int d = 0; d < 32; d++) acc[d] = fmaf(p, vr[d], acc[d]);
        }
        mx = nm;
    }
    float inv = 1.f / sum;

    __half* op = g_attn_h + ((size_t)b_*64 + n)*CDIM + hh*32;
#pragma unroll
    for (int d = 0; d < 32; d += 2)
        *(__half2*)(op + d) = __floats2half2_rn(acc[d]*inv, acc[d+1]*inv);
}

// ---------------- launch ----------------
extern "C" void kernel_launch(void* const* d_in, const int* in_sizes, int n_in,
                              void* d_out, int out_size){
    const float* x      = (const float*)d_in[0];
    const float* qkv_w  = (const float*)d_in[1];
    const float* q_bias = (const float*)d_in[2];
    const float* v_bias = (const float*)d_in[3];
    const float* lscale = (const float*)d_in[4];
    const float* cpb_w1 = (const float*)d_in[5];
    const float* cpb_b1 = (const float*)d_in[6];
    const float* cpb_w2 = (const float*)d_in[7];
    const float* proj_w = (const float*)d_in[8];
    const float* proj_b = (const float*)d_in[9];
    const float* n1s    = (const float*)d_in[10];
    const float* n1b    = (const float*)d_in[11];
    const float* n2s    = (const float*)d_in[12];
    const float* n2b    = (const float*)d_in[13];
    const float* fc1_w  = (const float*)d_in[14];
    const float* fc1_b  = (const float*)d_in[15];
    const float* fc2_w  = (const float*)d_in[16];
    const float* fc2_b  = (const float*)d_in[17];
    float* out = (float*)d_out;

    void *p_xh, *p_attn_h, *p_x1, *p_x1h, *p_hidh;
    void *p_wq, *p_wp, *p_w1, *p_w2;
    cudaGetSymbolAddress(&p_xh,     g_xh);
    cudaGetSymbolAddress(&p_attn_h, g_attn_h);
    cudaGetSymbolAddress(&p_x1,     g_x1);
    cudaGetSymbolAddress(&p_x1h,    g_x1h);
    cudaGetSymbolAddress(&p_hidh,   g_hidh);
    cudaGetSymbolAddress(&p_wq,     g_wq);
    cudaGetSymbolAddress(&p_wp,     g_wp);
    cudaGetSymbolAddress(&p_w1,     g_w1);
    cudaGetSymbolAddress(&p_w2,     g_w2);

    cudaFuncSetAttribute(gemm_h<1,1>, cudaFuncAttributeMaxDynamicSharedMemorySize, SMEM_GEMM);
    cudaFuncSetAttribute(gemm_h_qkv,  cudaFuncAttributeMaxDynamicSharedMemorySize, SMEM_GEMM);
    cudaFuncSetAttribute(gemm_ln<1>,  cudaFuncAttributeMaxDynamicSharedMemorySize, SMEM_LN);
    cudaFuncSetAttribute(gemm_ln<0>,  cudaFuncAttributeMaxDynamicSharedMemorySize, SMEM_LN);

    // 0: gather + x->fp16
    k_setup<<<(ROWS*CDIM/4)/256, 256>>>(x);
    // 1: CPB MLP + rpb
    k_cpb_rpb<<<1, 256>>>(cpb_w1, cpb_b1, cpb_w2);
    // 2: all weight transposes (fp16)
    k_transpose_all<<<dim3(32, 32, 4), dim3(32, 8)>>>(qkv_w, proj_w, fc1_w, fc2_w);
    // 3: QKV (131072 x 256) @ (256 x 768)
    gemm_h_qkv<<<dim3(6, ROWS/128), 256, SMEM_GEMM>>>((const __half*)p_xh,
            (const __half*)p_wq, q_bias, v_bias);
    // 4: attention
    k_attn<<<dim3(BWIN, NHEADS), 64>>>(lscale);
    // 5: proj + LN1 + residual + scatter (fused)   <- ncu -s 5 lands here
    gemm_ln<1><<<ROWS/128, 512, SMEM_LN>>>((const __half*)p_attn_h,
            (const __half*)p_wp, proj_b, x, n1s, n1b,
            (float*)p_x1, (__half*)p_x1h, 256);
    // 6: FC1 + GELU -> fp16
    gemm_h<1,1><<<dim3(8, ROWS/128), 256, SMEM_GEMM>>>((const __half*)p_x1h,
            (const __half*)p_w1, fc1_b, p_hidh, 256, 1024);
    // 7: FC2 + LN2 + residual -> out (fused)
    gemm_ln<0><<<ROWS/128, 512, SMEM_LN>>>((const __half*)p_hidh,
            (const __half*)p_w2, fc2_b, (const float*)p_x1, n2s, n2b,
            out, (__half*)nullptr, 1024);
}